// round 14
// baseline (speedup 1.0000x reference)
#include <cuda_runtime.h>
#include <math.h>

#define BB 8
#define NN 400
#define DD 768
#define CC 3
#define MM 160
#define NPAIR (MM*(MM-1))          // 25440
#define PROB_ELEMS (BB*NPAIR*CC)   // 610560

// ---------------- scratch (static device globals; no allocation) ----------------
__device__ float  g_s[BB*NN];
__device__ int    g_pos[BB*MM];
__device__ float  g_xr[BB*MM*DD];
__device__ int    g_rr[BB*MM*2];
__device__ float  g_ab[BB*MM*6];   // a[0..2], b[0..2] per (b,m), no bias
__device__ float  g_wt[CC*DD];     // w3 transposed: g_wt[c*DD+d] = wp[(2D+d)*3+c]

// symmetric tile-pair enumeration (5x5 tiles, ti<=tj): 15 pairs
__constant__ int c_ti[15] = {0,0,0,0,0,1,1,1,1,2,2,2,3,3,4};
__constant__ int c_tj[15] = {0,1,2,3,4,1,2,3,4,2,3,4,3,4,4};

// ---------------- K1: span dot (f32, warp per row, grid-wide) + w3 transpose ----
__global__ void k_span(const float* __restrict__ x, const float* __restrict__ w,
                       const float* __restrict__ wp) {
    // blocks 0..5 also produce the transposed w3 (2304 values, 3 per thread)
    if (blockIdx.x < 6) {
        int base = blockIdx.x * 384 + threadIdx.x * 3;
        #pragma unroll
        for (int q = 0; q < 3; q++) {
            int id = base + q;                 // id = c*DD + d
            int c = id / DD, d = id % DD;
            g_wt[id] = wp[(2*DD + d)*CC + c];
        }
    }
    int row = blockIdx.x * 4 + (threadIdx.x >> 5);   // 0 .. 3199
    int lane = threadIdx.x & 31;
    const float4* xr = (const float4*)(x + (size_t)row * DD);
    const float4* wr = (const float4*)w;
    float acc = 0.f;
    #pragma unroll
    for (int i = 0; i < DD/128; i++) {
        float4 v = xr[i*32 + lane];
        float4 u = wr[i*32 + lane];
        acc = fmaf(v.x, u.x, acc);
        acc = fmaf(v.y, u.y, acc);
        acc = fmaf(v.z, u.z, acc);
        acc = fmaf(v.w, u.w, acc);
    }
    #pragma unroll
    for (int o = 16; o; o >>= 1) acc += __shfl_down_sync(0xffffffffu, acc, o);
    if (lane == 0) g_s[row] = acc;
}

// ---------------- K2: rank + position selection (uint32 keys, parallel) ---------
__global__ void k_select() {
    int b = blockIdx.x;
    __shared__ unsigned int key[NN];
    __shared__ int flags[NN];
    __shared__ int wsum[16];
    int t = threadIdx.x;     // 512 threads
    if (t < NN) {
        int u = __float_as_int(g_s[b*NN + t]);
        unsigned int k = (u < 0) ? ~(unsigned int)u : ((unsigned int)u | 0x80000000u);
        key[t] = k;
        flags[t] = 0;
    }
    __syncthreads();
    if (t < MM) {
        unsigned int v = key[t];
        int rank = 0;
        for (int k2 = 0; k2 < NN; k2++) {
            unsigned int u = key[k2];
            rank += (u > v) || (u == v && k2 < t);
        }
        flags[rank] = 1;
    }
    __syncthreads();
    int f = (t < NN) ? flags[t] : 0;
    unsigned mask = __ballot_sync(0xffffffffu, f);
    int lane = t & 31, w = t >> 5;
    if (lane == 0) wsum[w] = __popc(mask);
    __syncthreads();
    if (t == 0) {
        int run = 0;
        for (int i = 0; i < 16; i++) { int c = wsum[i]; wsum[i] = run; run += c; }
    }
    __syncthreads();
    if (f) {
        int idx = wsum[w] + __popc(mask & ((1u << lane) - 1));
        g_pos[b*MM + idx] = t;
    }
}

// ---------------- K3: gather x_ranked, ranges, and a/b projections -------------
__global__ void k_gather(const float* __restrict__ x, const float* __restrict__ wp,
                         const int* __restrict__ ranges) {
    int m = blockIdx.x, b = blockIdx.y;
    int p = g_pos[b*MM + m];
    const float4* src = (const float4*)(x + (size_t)(b*NN + p) * DD);
    float4* dst = (float4*)(g_xr + (size_t)(b*MM + m) * DD);
    float acc[6] = {0,0,0,0,0,0};
    for (int t = threadIdx.x; t < DD/4; t += blockDim.x) {
        float4 v = src[t];
        dst[t] = v;
        int d = t * 4;
        float vv[4] = {v.x, v.y, v.z, v.w};
        #pragma unroll
        for (int q = 0; q < 4; q++) {
            #pragma unroll
            for (int c = 0; c < CC; c++) {
                acc[c]     += vv[q] * wp[(d + q) * CC + c];
                acc[3 + c] += vv[q] * wp[(DD + d + q) * CC + c];
            }
        }
    }
    __shared__ float sh[6][4];
    #pragma unroll
    for (int r = 0; r < 6; r++) {
        float a = acc[r];
        #pragma unroll
        for (int o = 16; o; o >>= 1) a += __shfl_down_sync(0xffffffffu, a, o);
        if ((threadIdx.x & 31) == 0) sh[r][threadIdx.x >> 5] = a;
    }
    __syncthreads();
    if (threadIdx.x < 6)
        g_ab[(b*MM + m)*6 + threadIdx.x] =
            sh[threadIdx.x][0] + sh[threadIdx.x][1] + sh[threadIdx.x][2] + sh[threadIdx.x][3];
    if (threadIdx.x < 2)
        g_rr[(b*MM + m)*2 + threadIdx.x] = ranges[p*2 + threadIdx.x];
}

// ---------------- K4: symmetric tf32 pairwise logits + dual-orientation epilogue
// grid (15 tile-pairs, 8 batches). 32x32 tile, 384 thr (12 warps).
// warp role: channel c = wid%3, k-quarter kg = wid/3 (2 k8 per 64-chunk).
// A pre-scaled by w3[:,c] at load (3 smem copies). Inner loop: 8 LDS.64 + 8 MMA.
// G is symmetric -> each block emits both (i,j) and (j,i).
#define TILE 32
#define KCH 64
#define XS 72      // 72 mod 32 == 8 (same conflict class as proven XS=136)
#define CSP 34     // Cs row stride (even -> float2-aligned)

__device__ __forceinline__ void mma_tf32(float* d,
        float a0, float a1, float a2, float a3, float b0, float b1) {
    asm volatile(
        "mma.sync.aligned.m16n8k8.row.col.f32.tf32.tf32.f32 "
        "{%0,%1,%2,%3}, {%4,%5,%6,%7}, {%8,%9}, {%0,%1,%2,%3};\n"
        : "+f"(d[0]), "+f"(d[1]), "+f"(d[2]), "+f"(d[3])
        : "r"(__float_as_uint(a0)), "r"(__float_as_uint(a1)),
          "r"(__float_as_uint(a2)), "r"(__float_as_uint(a3)),
          "r"(__float_as_uint(b0)), "r"(__float_as_uint(b1)));
}

__global__ void __launch_bounds__(384)
k_pairs(const float* __restrict__ bpair, float* __restrict__ out) {
    __shared__ union {
        struct { float xis[CC][TILE][XS]; float xj[TILE][XS]; } a;   // 36864 B
        float cs[CC][TILE][CSP];                                      // 13056 B
    } sm;

    int b = blockIdx.y;
    int ibase = c_ti[blockIdx.x] * TILE;
    int jbase = c_tj[blockIdx.x] * TILE;
    int tid = threadIdx.x;
    int wid = tid >> 5, lane = tid & 31;
    int c  = wid % 3;
    int kg = wid / 3;            // 0..3, k-quarter within each 64-chunk
    int grp = lane >> 2, tig = lane & 3;

    float acc[2][4][4];
    #pragma unroll
    for (int mi = 0; mi < 2; mi++)
        #pragma unroll
        for (int nb = 0; nb < 4; nb++)
            #pragma unroll
            for (int q = 0; q < 4; q++) acc[mi][nb][q] = 0.f;

    const float* xrb = g_xr + (size_t)b * MM * DD;

    for (int ch = 0; ch < DD / KCH; ch++) {
        int dbase = ch * KCH;
        // load Xi (scaled x3 channels) + Xj (raw), permuted scatter
        for (int e = tid; e < 2 * TILE * (KCH/4); e += 384) {
            int r = (e >> 4) & 31, c4 = e & 15;
            int d0 = c4 * 4;
            int pos = ((d0 >> 3) << 3) + ((d0 >> 2) & 1);   // k8*8 + half
            if (e < 512) {
                float4 v = *(const float4*)(xrb + (size_t)(ibase + r) * DD + dbase + d0);
                #pragma unroll
                for (int cc = 0; cc < CC; cc++) {
                    float4 w = *(const float4*)(g_wt + cc*DD + dbase + d0);
                    sm.a.xis[cc][r][pos]     = v.x * w.x;
                    sm.a.xis[cc][r][pos + 2] = v.y * w.y;
                    sm.a.xis[cc][r][pos + 4] = v.z * w.z;
                    sm.a.xis[cc][r][pos + 6] = v.w * w.w;
                }
            } else {
                float4 v = *(const float4*)(xrb + (size_t)(jbase + r) * DD + dbase + d0);
                sm.a.xj[r][pos]     = v.x;
                sm.a.xj[r][pos + 2] = v.y;
                sm.a.xj[r][pos + 4] = v.z;
                sm.a.xj[r][pos + 6] = v.w;
            }
        }
        __syncthreads();

        #pragma unroll
        for (int kq = 0; kq < 2; kq++) {
            int off = (kg * 2 + kq) * 8 + tig * 2;
            float2 a0 = *(const float2*)&sm.a.xis[c][grp][off];
            float2 a1 = *(const float2*)&sm.a.xis[c][grp + 8][off];
            float2 a2 = *(const float2*)&sm.a.xis[c][grp + 16][off];
            float2 a3 = *(const float2*)&sm.a.xis[c][grp + 24][off];
            float2 b0 = *(const float2*)&sm.a.xj[grp][off];
            float2 b1 = *(const float2*)&sm.a.xj[grp + 8][off];
            float2 b2 = *(const float2*)&sm.a.xj[grp + 16][off];
            float2 b3 = *(const float2*)&sm.a.xj[grp + 24][off];
            mma_tf32(acc[0][0], a0.x, a1.x, a0.y, a1.y, b0.x, b0.y);
            mma_tf32(acc[0][1], a0.x, a1.x, a0.y, a1.y, b1.x, b1.y);
            mma_tf32(acc[0][2], a0.x, a1.x, a0.y, a1.y, b2.x, b2.y);
            mma_tf32(acc[0][3], a0.x, a1.x, a0.y, a1.y, b3.x, b3.y);
            mma_tf32(acc[1][0], a2.x, a3.x, a2.y, a3.y, b0.x, b0.y);
            mma_tf32(acc[1][1], a2.x, a3.x, a2.y, a3.y, b1.x, b1.y);
            mma_tf32(acc[1][2], a2.x, a3.x, a2.y, a3.y, b2.x, b2.y);
            mma_tf32(acc[1][3], a2.x, a3.x, a2.y, a3.y, b3.x, b3.y);
        }
        __syncthreads();
    }

    // combine the 4 kg partials into Cs (sequential store/add, uniform barriers)
    #pragma unroll
    for (int g = 0; g < 4; g++) {
        if (kg == g) {
            #pragma unroll
            for (int mi = 0; mi < 2; mi++)
                #pragma unroll
                for (int nb = 0; nb < 4; nb++) {
                    int row = mi*16 + grp, col = nb*8 + tig*2;
                    float2* p0 = (float2*)&sm.cs[c][row][col];
                    float2* p1 = (float2*)&sm.cs[c][row + 8][col];
                    float2 v0 = make_float2(acc[mi][nb][0], acc[mi][nb][1]);
                    float2 v1 = make_float2(acc[mi][nb][2], acc[mi][nb][3]);
                    if (g == 0) { *p0 = v0; *p1 = v1; }
                    else {
                        float2 t0 = *p0; t0.x += v0.x; t0.y += v0.y; *p0 = t0;
                        float2 t1 = *p1; t1.x += v1.x; t1.y += v1.y; *p1 = t1;
                    }
                }
        }
        __syncthreads();
    }

    float bp0 = bpair[0], bp1 = bpair[1], bp2 = bpair[2];
    bool diag = (ibase == jbase);
    for (int p = tid; p < TILE * TILE; p += 384) {
        int i = p >> 5, j = p & 31;
        if (diag && i == j) continue;
        float G0 = sm.cs[0][i][j], G1 = sm.cs[1][i][j], G2 = sm.cs[2][i][j];
        int gi = ibase + i, gj = jbase + j;
        const float* abI = &g_ab[(b*MM + gi)*6];
        const float* abJ = &g_ab[(b*MM + gj)*6];
        const int* ri = &g_rr[(b*MM + gi)*2];
        const int* rj = &g_rr[(b*MM + gj)*2];

        // orientation (gi -> gj)
        {
            float l0 = G0 + abI[0] + abJ[3] + bp0;
            float l1 = G1 + abI[1] + abJ[4] + bp1;
            float l2 = G2 + abI[2] + abJ[5] + bp2;
            float s0 = 1.f / (1.f + expf(-l0));
            float s1 = 1.f / (1.f + expf(-l1));
            float s2 = 1.f / (1.f + expf(-l2));
            float mx = fmaxf(s0, fmaxf(s1, s2));
            float e0 = expf(s0 - mx), e1 = expf(s1 - mx), e2 = expf(s2 - mx);
            float inv = 1.f / (e0 + e1 + e2);
            int pidx = gi * (MM - 1) + gj - (gj > gi ? 1 : 0);
            size_t po = (size_t)b * NPAIR + pidx;
            float* o = out + po * 3;
            o[0] = e0 * inv; o[1] = e1 * inv; o[2] = e2 * inv;
            ((float4*)(out + PROB_ELEMS))[po] =
                make_float4((float)ri[0], (float)ri[1], (float)rj[0], (float)rj[1]);
        }
        // orientation (gj -> gi), same symmetric G
        if (!diag) {
            float l0 = G0 + abJ[0] + abI[3] + bp0;
            float l1 = G1 + abJ[1] + abI[4] + bp1;
            float l2 = G2 + abJ[2] + abI[5] + bp2;
            float s0 = 1.f / (1.f + expf(-l0));
            float s1 = 1.f / (1.f + expf(-l1));
            float s2 = 1.f / (1.f + expf(-l2));
            float mx = fmaxf(s0, fmaxf(s1, s2));
            float e0 = expf(s0 - mx), e1 = expf(s1 - mx), e2 = expf(s2 - mx);
            float inv = 1.f / (e0 + e1 + e2);
            int pidx = gj * (MM - 1) + gi - (gi > gj ? 1 : 0);
            size_t po = (size_t)b * NPAIR + pidx;
            float* o = out + po * 3;
            o[0] = e0 * inv; o[1] = e1 * inv; o[2] = e2 * inv;
            ((float4*)(out + PROB_ELEMS))[po] =
                make_float4((float)rj[0], (float)rj[1], (float)ri[0], (float)ri[1]);
        }
    }
}

// ---------------- launcher ------------------------------------------------------
extern "C" void kernel_launch(void* const* d_in, const int* in_sizes, int n_in,
                              void* d_out, int out_size) {
    const float* x      = (const float*)d_in[0];
    const float* w_span = (const float*)d_in[1];
    // d_in[2] = b_span (monotonic shift: irrelevant to ordering)
    const float* w_pair = (const float*)d_in[3];
    const float* b_pair = (const float*)d_in[4];
    const int*   ranges = (const int*)d_in[5];
    float* out = (float*)d_out;

    k_span<<<BB * NN / 4, 128>>>(x, w_span, w_pair);
    k_select<<<BB, 512>>>();
    {
        dim3 g(MM, BB);
        k_gather<<<g, 128>>>(x, w_pair, ranges);
    }
    {
        dim3 g(15, BB);   // symmetric tile pairs x batches = 120 blocks
        k_pairs<<<g, 384>>>(b_pair, out);
    }
}